// round 2
// baseline (speedup 1.0000x reference)
#include <cuda_runtime.h>
#include <cstdint>

// LMN layer, persistent-kernel formulation (2 graph nodes total):
//   node 1: prologue GEMM  xW[t,b,:] = x[t,b,:] @ Wxh^T + bh   (32768 CTAs)
//   node 2: persistent recurrence kernel (128 CTAs, 1/SM, co-resident):
//     per step t:  phase1: CTAs 0-63:  h = tanh(xW[t] + m@Wmh^T)  (16 cols each)
//                          CTAs 64-127: c2 = m@Wmm^T              (16 cols each)
//                  grid_sync
//                  phase2: all CTAs:   m' = h@Whm^T + c2 + bm     (8 cols each)
//                  grid_sync
//   Weight slices stay SMEM-resident across all 512 steps.
//   Inner loop: k-pair packed f32x2 FMA (no splats), reg-double-buffered staging.

#define T_STEPS 512
#define DIM     1024
#define STEP    (64 * 1024)
#define OUTS    (T_STEPS * STEP)

typedef unsigned long long ull;

__device__ float g_xW[(size_t)T_STEPS * STEP];   // 128 MB
__device__ float g_h [STEP];
__device__ float g_c2[STEP];
__device__ unsigned g_cnt = 0;
__device__ unsigned g_gen = 0;

__device__ __forceinline__ void ffma2(ull& d, ull a, ull b) {
    asm("fma.rn.f32x2 %0, %1, %2, %0;" : "+l"(d) : "l"(a), "l"(b));
}
__device__ __forceinline__ float merge2(ull v) {
    float lo = __uint_as_float((unsigned)(v & 0xffffffffull));
    float hi = __uint_as_float((unsigned)(v >> 32));
    return lo + hi;
}

constexpr int AST    = 34;                 // A-stage row stride (floats, even)
constexpr int WSTR   = 1026;               // weight row stride  (floats, even)
constexpr int STAGEF = 4 * 64 * AST;       // 8704 floats

// ---------------------------------------------------------------------------
// One 64xBN GEMM tile: C[row, col] = sum_k A[row,k] * Wsm[col,k]
// 256 threads = 4 k-groups (K split 256 each) x 64 positions.
// Per-thread tile: 4 rows x TC cols. Both operands read as f32x2 k-pairs;
// acc holds even-k sum in lo, odd-k in hi; merged in the epilogue, then
// cross-group smem reduction feeds epi(row, col, sum).
// ---------------------------------------------------------------------------
template<int BN, int TC, class Epi>
__device__ __forceinline__ void gemm_step(const float* __restrict__ A,
                                          const float* __restrict__ wsm,
                                          float* __restrict__ stage,
                                          Epi epi)
{
    constexpr int TRTC = 4 * TC;          // outputs per thread (16 or 8)
    const int tid = threadIdx.x;
    const int kg  = tid >> 6;             // k-group 0..3
    const int g   = tid & 63;             // position within group
    const int pr  = g >> 2;               // rows 4pr..4pr+3
    const int pc  = g & 3;                // cols TC*pc..TC*pc+TC-1
    float* st = stage + kg * (64 * AST);
    const int kbase = kg << 8;            // 256 k per group

    ull acc[4][TC];
    #pragma unroll
    for (int r = 0; r < 4; ++r)
        #pragma unroll
        for (int c = 0; c < TC; ++c) acc[r][c] = 0ull;

    // register-prefetch chunk 0 (8 independent float4 LDGs per thread)
    float4 pf[8];
    #pragma unroll
    for (int j = 0; j < 8; ++j) {
        int idx = j * 64 + g, b = idx >> 3, k4 = idx & 7;
        pf[j] = *(const float4*)(A + (size_t)b * DIM + kbase + k4 * 4);
    }

    for (int ch = 0; ch < 8; ++ch) {
        __syncthreads();                  // prior chunk's reads done
        #pragma unroll
        for (int j = 0; j < 8; ++j) {     // regs -> smem  [b][kloc]
            int idx = j * 64 + g, b = idx >> 3, k4 = idx & 7;
            float* p = st + b * AST + k4 * 4;
            p[0] = pf[j].x; p[1] = pf[j].y; p[2] = pf[j].z; p[3] = pf[j].w;
        }
        __syncthreads();
        if (ch < 7) {                     // prefetch next chunk during compute
            int k0 = kbase + (ch + 1) * 32;
            #pragma unroll
            for (int j = 0; j < 8; ++j) {
                int idx = j * 64 + g, b = idx >> 3, k4 = idx & 7;
                pf[j] = *(const float4*)(A + (size_t)b * DIM + k0 + k4 * 4);
            }
        }
        const float* wk = wsm + (TC * pc) * WSTR + kbase + ch * 32;
        #pragma unroll
        for (int kk = 0; kk < 16; ++kk) {
            ull a2[4];
            #pragma unroll
            for (int r = 0; r < 4; ++r)
                a2[r] = *(const ull*)(st + (4 * pr + r) * AST + 2 * kk);
            #pragma unroll
            for (int c = 0; c < TC; ++c) {
                ull w2 = *(const ull*)(wk + c * WSTR + 2 * kk);
                #pragma unroll
                for (int r = 0; r < 4; ++r) ffma2(acc[r][c], a2[r], w2);
            }
        }
    }
    __syncthreads();

    // partials -> smem (alias over stage), cross-group reduce, epilogue
    float* red = stage;
    #pragma unroll
    for (int r = 0; r < 4; ++r)
        #pragma unroll
        for (int c = 0; c < TC; ++c)
            red[tid * TRTC + r * TC + c] = merge2(acc[r][c]);
    __syncthreads();

    #pragma unroll
    for (int e = tid; e < 64 * BN; e += 256) {
        int pos = e / TRTC, elem = e % TRTC;
        float s = 0.f;
        #pragma unroll
        for (int gg = 0; gg < 4; ++gg)
            s += red[(gg * 64 + pos) * TRTC + elem];
        int row = 4 * (pos >> 2) + elem / TC;
        int col = TC * (pos & 3) + elem % TC;
        epi(row, col, s);
    }
    __syncthreads();
}

__device__ __forceinline__ void load_wslice(float* wsm,
                                            const float* __restrict__ W,
                                            int ncols, int tid)
{
    for (int e = tid; e < ncols * DIM; e += 256) {
        int c = e >> 10, k = e & 1023;
        wsm[c * WSTR + k] = W[(size_t)c * DIM + k];
    }
}

// fenced sense-counting grid barrier (128 co-resident CTAs)
__device__ __forceinline__ void grid_sync()
{
    __syncthreads();
    if (threadIdx.x == 0) {
        unsigned gen;
        asm volatile("ld.acquire.gpu.u32 %0, [%1];" : "=r"(gen) : "l"(&g_gen));
        __threadfence();
        unsigned prev = atomicAdd(&g_cnt, 1u);
        if (prev == gridDim.x - 1) {
            g_cnt = 0;
            asm volatile("st.release.gpu.u32 [%0], %1;"
                         :: "l"(&g_gen), "r"(gen + 1) : "memory");
        } else {
            unsigned cur;
            do {
                asm volatile("ld.acquire.gpu.u32 %0, [%1];"
                             : "=r"(cur) : "l"(&g_gen));
            } while (cur == gen);
        }
    }
    __syncthreads();
}

// ------------------------- prologue: xW = x @ Wxh^T + bh -------------------
__global__ void __launch_bounds__(256) prologue_k(const float* __restrict__ x,
                                                  const float* __restrict__ Wxh,
                                                  const float* __restrict__ bh)
{
    extern __shared__ float sm[];
    float* w1s   = sm;                        // [16][1026]
    float* stage = sm + 16 * WSTR;
    const int tid = threadIdx.x;
    load_wslice(w1s, Wxh + (size_t)blockIdx.x * 16 * DIM, 16, tid);
    __syncthreads();
    const float* A = x + (size_t)blockIdx.y * 64 * DIM;
    float* orow    = g_xW + (size_t)blockIdx.y * 64 * DIM;
    const int nb   = blockIdx.x * 16;
    gemm_step<16, 4>(A, w1s, stage, [&](int row, int col, float s) {
        int n = nb + col;
        orow[(size_t)row * DIM + n] = s + bh[n];
    });
}

// ------------------------- persistent recurrence ---------------------------
__global__ void __launch_bounds__(256) recur_k(const float* __restrict__ m_prev,
                                               const float* __restrict__ Whm,
                                               const float* __restrict__ Wmm,
                                               const float* __restrict__ Wmh,
                                               const float* __restrict__ bm,
                                               float* __restrict__ out)
{
    extern __shared__ float sm[];
    float* w1s   = sm;                        // [16][1026]  phase-1 weights
    float* w2s   = sm + 16 * WSTR;            // [ 8][1026]  Whm slice
    float* stage = sm + 24 * WSTR;
    const int b = blockIdx.x, tid = threadIdx.x;

    const float* W1 = (b < 64) ? (Wmh + (size_t)b * 16 * DIM)
                               : (Wmm + (size_t)(b - 64) * 16 * DIM);
    load_wslice(w1s, W1, 16, tid);
    load_wslice(w2s, Whm + (size_t)b * 8 * DIM, 8, tid);
    __syncthreads();

    const int nb1 = (b & 63) * 16;
    const int nb2 = b * 8;

    for (int t = 0; t < T_STEPS; ++t) {
        const float* A   = t ? (out + (size_t)(t - 1) * STEP) : m_prev;
        const float* xwt = g_xW + (size_t)t * STEP;

        if (b < 64) {
            gemm_step<16, 4>(A, w1s, stage, [&](int row, int col, float s) {
                int n = nb1 + col;
                g_h[row * DIM + n] = tanhf(xwt[(size_t)row * DIM + n] + s);
            });
        } else {
            gemm_step<16, 4>(A, w1s, stage, [&](int row, int col, float s) {
                g_c2[row * DIM + nb1 + col] = s;
            });
        }
        grid_sync();

        float* ot = out + (size_t)t * STEP;
        gemm_step<8, 2>(g_h, w2s, stage, [&](int row, int col, float s) {
            int n = nb2 + col;
            float v = s + g_c2[row * DIM + n] + bm[n];
            ot[(size_t)row * DIM + n] = v;
            if (t == T_STEPS - 1)
                out[(size_t)OUTS + (size_t)row * DIM + n] = v;   // m_final
        });
        grid_sync();
    }
}

#define PRO_SMEM ((16 * WSTR + STAGEF) * 4)   // 100480 B
#define PER_SMEM ((24 * WSTR + STAGEF) * 4)   // 133312 B

extern "C" void kernel_launch(void* const* d_in, const int* in_sizes, int n_in,
                              void* d_out, int out_size)
{
    const float* x      = (const float*)d_in[0];
    const float* m_prev = (const float*)d_in[1];
    const float* Wxh    = (const float*)d_in[2];
    const float* Whm    = (const float*)d_in[3];
    const float* Wmm    = (const float*)d_in[4];
    const float* Wmh    = (const float*)d_in[5];
    const float* bh     = (const float*)d_in[6];
    const float* bm     = (const float*)d_in[7];
    float* out = (float*)d_out;

    cudaFuncSetAttribute(prologue_k,
                         cudaFuncAttributeMaxDynamicSharedMemorySize, PRO_SMEM);
    cudaFuncSetAttribute(recur_k,
                         cudaFuncAttributeMaxDynamicSharedMemorySize, PER_SMEM);

    prologue_k<<<dim3(64, 512), 256, PRO_SMEM>>>(x, Wxh, bh);
    recur_k<<<128, 256, PER_SMEM>>>(m_prev, Whm, Wmm, Wmh, bm, out);
}

// round 3
// speedup vs baseline: 1.0207x; 1.0207x over previous
#include <cuda_runtime.h>
#include <cstdint>

// LMN layer, persistent formulation, round 3:
//   node 1: prologue GEMM  xW = x @ Wxh^T + bh
//   node 2: persistent recurrence (128 CTAs x 512 thr, 1 CTA/SM):
//     phase1: CTAs 0-63:  h = tanh(xW[t] + m@Wmh^T)   (16 cols each)
//             CTAs 64-127: c2 = m@Wmm^T               (16 cols each)
//     grid_sync
//     phase2: all CTAs:   m' = h@Whm^T + c2 + bm      (8 cols each)
//     grid_sync
// Core: f32x2 FMA, LDS.128 operands, XOR-swizzled double-buffered staging,
// one __syncthreads per 32-k chunk, 16 warps/SM.

#define T_STEPS 512
#define DIM     1024
#define STEP    (64 * 1024)
#define OUTS    (T_STEPS * STEP)

typedef unsigned long long ull;

__device__ float g_xW[(size_t)T_STEPS * STEP];   // 128 MB
__device__ float g_h [STEP];
__device__ float g_c2[STEP];
__device__ unsigned g_cnt = 0;
__device__ unsigned g_gen = 0;

__device__ __forceinline__ void ffma2(ull& d, ull a, ull b) {
    asm("fma.rn.f32x2 %0, %1, %2, %0;" : "+l"(d) : "l"(a), "l"(b));
}
__device__ __forceinline__ float merge2(ull v) {
    float lo, hi;
    asm("mov.b64 {%0, %1}, %2;" : "=f"(lo), "=f"(hi) : "l"(v));
    return lo + hi;
}

constexpr int WSTR      = 1028;             // weight row stride (floats)
constexpr int STAGE_GRP = 2 * 64 * 32;      // per k-group: 2 bufs x 64 rows x 32
constexpr int STAGE_TOT = 4 * STAGE_GRP;    // 16384 floats = 64 KB

// ---------------------------------------------------------------------------
// 64 x (8*C) GEMM tile:  C[row,col] = sum_k A[row,k] * wsm[col*WSTR + k]
// 512 threads = 4 k-groups (256 k each) x 128 positions (16 row-quads x 8 pc).
// Thread tile: 4 rows x C cols; f32x2 accumulators (even k in lo, odd in hi).
// Stage layout per chunk: row*32 floats, float4 col = k4 ^ ((row>>2)&7)
// (conflict-free LDS.128/STS.128, one XOR per q shared by 4 row loads).
// ---------------------------------------------------------------------------
template<int C, class Epi>
__device__ __forceinline__ void gemm_core(const float* __restrict__ A,
                                          const float* __restrict__ wsm,
                                          float* __restrict__ stage,
                                          Epi epi)
{
    constexpr int BN = 8 * C;
    constexpr int PT = 4 * C;                 // outputs per thread
    const int tid = threadIdx.x;
    const int kg  = tid >> 7;                 // k-group 0..3
    const int g   = tid & 127;
    const int wg  = g >> 5;                   // warp within group
    const int l   = g & 31;
    const int pr  = ((wg & 1) << 3) | (l >> 2);   // row-quad 0..15
    const int pc  = ((wg >> 1) << 2) | (l & 3);   // col-group 0..7
    const int prx = pr & 7;                   // swizzle key for this quad
    const int kbase = kg << 8;

    float* stg = stage + kg * STAGE_GRP;

    ull acc[4][C];
    #pragma unroll
    for (int r = 0; r < 4; ++r)
        #pragma unroll
        for (int c = 0; c < C; ++c) acc[r][c] = 0ull;

    // prefetch chunk 0: 4 LDG.128 per thread (coalesced 128B per row-octet)
    float4 pf[4];
    #pragma unroll
    for (int j = 0; j < 4; ++j) {
        int slot = j * 128 + g, b = slot >> 3, k4 = slot & 7;
        pf[j] = *(const float4*)(A + (size_t)b * DIM + kbase + k4 * 4);
    }

    for (int ch = 0; ch < 8; ++ch) {
        float* buf = stg + (ch & 1) * (64 * 32);
        #pragma unroll
        for (int j = 0; j < 4; ++j) {         // regs -> swizzled smem
            int slot = j * 128 + g, b = slot >> 3, k4 = slot & 7;
            *(float4*)(buf + b * 32 + ((k4 ^ ((b >> 2) & 7)) << 2)) = pf[j];
        }
        if (ch < 7) {                         // prefetch next chunk
            int k0 = kbase + (ch + 1) * 32;
            #pragma unroll
            for (int j = 0; j < 4; ++j) {
                int slot = j * 128 + g, b = slot >> 3, k4 = slot & 7;
                pf[j] = *(const float4*)(A + (size_t)b * DIM + k0 + k4 * 4);
            }
        }
        __syncthreads();                      // buf ready; other buf now free

        const float* ab = buf + pr * 128;     // rows 4pr.. (32 floats each)
        const float* wb = wsm + C * pc * WSTR + kbase + ch * 32;
        #pragma unroll
        for (int q = 0; q < 8; ++q) {
            const float* aq = ab + ((q ^ prx) << 2);
            ulonglong2 av[4];
            #pragma unroll
            for (int r = 0; r < 4; ++r)
                av[r] = *(const ulonglong2*)(aq + r * 32);
            #pragma unroll
            for (int c = 0; c < C; ++c) {
                ulonglong2 wv = *(const ulonglong2*)(wb + c * WSTR + q * 4);
                #pragma unroll
                for (int r = 0; r < 4; ++r) {
                    ffma2(acc[r][c], av[r].x, wv.x);
                    ffma2(acc[r][c], av[r].y, wv.y);
                }
            }
        }
    }
    __syncthreads();                          // all compute done; stage free

    // cross-k-group reduction through smem (aliases stage)
    float* red = stage;
    #pragma unroll
    for (int r = 0; r < 4; ++r)
        #pragma unroll
        for (int c = 0; c < C; ++c)
            red[(size_t)tid * PT + r * C + c] = merge2(acc[r][c]);
    __syncthreads();

    #pragma unroll
    for (int e = tid; e < 64 * BN; e += 512) {
        int row = e / BN, col = e % BN;       // row-major -> coalesced epi
        int pr2 = row >> 2, r = row & 3;
        int pcc = col / C,  c = col % C;
        int pos = (((pr2 >> 3) | (((pcc >> 2) & 1) << 1)) << 5)
                | ((pr2 & 7) << 2) | (pcc & 3);
        float s = 0.f;
        #pragma unroll
        for (int k = 0; k < 4; ++k)
            s += red[(size_t)((k << 7) + pos) * PT + r * C + c];
        epi(row, col, s);
    }
    __syncthreads();                          // protect red before next STS
}

__device__ __forceinline__ void load_wslice(float* wsm,
                                            const float* __restrict__ W,
                                            int ncols, int tid)
{
    for (int e = tid; e < ncols * DIM; e += 512) {
        int c = e >> 10, k = e & 1023;
        wsm[c * WSTR + k] = W[(size_t)c * DIM + k];
    }
}

// fenced sense-counting grid barrier (128 co-resident CTAs)
__device__ __forceinline__ void grid_sync()
{
    __syncthreads();
    if (threadIdx.x == 0) {
        unsigned gen;
        asm volatile("ld.acquire.gpu.u32 %0, [%1];" : "=r"(gen) : "l"(&g_gen));
        __threadfence();
        unsigned prev = atomicAdd(&g_cnt, 1u);
        if (prev == gridDim.x - 1) {
            g_cnt = 0;
            asm volatile("st.release.gpu.u32 [%0], %1;"
                         :: "l"(&g_gen), "r"(gen + 1) : "memory");
        } else {
            unsigned cur;
            do {
                asm volatile("ld.acquire.gpu.u32 %0, [%1];"
                             : "=r"(cur) : "l"(&g_gen));
            } while (cur == gen);
        }
    }
    __syncthreads();
}

// ------------------------- prologue: xW = x @ Wxh^T + bh -------------------
__global__ void __launch_bounds__(512) prologue_k(const float* __restrict__ x,
                                                  const float* __restrict__ Wxh,
                                                  const float* __restrict__ bh)
{
    extern __shared__ float sm[];
    float* w1s   = sm;                        // [16][1028]
    float* stage = sm + 16 * WSTR;
    load_wslice(w1s, Wxh + (size_t)blockIdx.x * 16 * DIM, 16, threadIdx.x);
    __syncthreads();
    const float* A = x + (size_t)blockIdx.y * 64 * DIM;
    float* orow    = g_xW + (size_t)blockIdx.y * 64 * DIM;
    const int nb   = blockIdx.x * 16;
    gemm_core<2>(A, w1s, stage, [&](int row, int col, float s) {
        int n = nb + col;
        orow[(size_t)(row << 10) + n] = s + bh[n];
    });
}

// ------------------------- persistent recurrence ---------------------------
__global__ void __launch_bounds__(512) recur_k(const float* __restrict__ m_prev,
                                               const float* __restrict__ Whm,
                                               const float* __restrict__ Wmm,
                                               const float* __restrict__ Wmh,
                                               const float* __restrict__ bm,
                                               float* __restrict__ out)
{
    extern __shared__ float sm[];
    float* w1s   = sm;                        // [16][1028] phase-1 weights
    float* w2s   = sm + 16 * WSTR;            // [ 8][1028] Whm slice
    float* stage = sm + 24 * WSTR;
    const int b = blockIdx.x, tid = threadIdx.x;

    const float* W1 = (b < 64) ? (Wmh + (size_t)b * 16 * DIM)
                               : (Wmm + (size_t)(b - 64) * 16 * DIM);
    load_wslice(w1s, W1, 16, tid);
    load_wslice(w2s, Whm + (size_t)b * 8 * DIM, 8, tid);
    __syncthreads();

    const int nb1  = (b & 63) * 16;
    const int nb2  = b * 8;
    const bool hchk = (b < 64);

    for (int t = 0; t < T_STEPS; ++t) {
        const float* A   = t ? (out + (size_t)(t - 1) * STEP) : m_prev;
        const float* xwt = g_xW + (size_t)t * STEP;

        gemm_core<2>(A, w1s, stage, [&](int row, int col, float s) {
            int n = (row << 10) + nb1 + col;
            if (hchk) g_h[n] = tanhf(xwt[n] + s);
            else      g_c2[n] = s;
        });
        grid_sync();

        float* ot = out + (size_t)t * STEP;
        gemm_core<1>(g_h, w2s, stage, [&](int row, int col, float s) {
            int n = (row << 10) + nb2 + col;
            float v = s + g_c2[n] + bm[nb2 + col];
            ot[n] = v;
            if (t == T_STEPS - 1) out[(size_t)OUTS + n] = v;   // m_final
        });
        grid_sync();
    }
}

#define PRO_SMEM ((16 * WSTR + STAGE_TOT) * 4)   // 131328 B
#define PER_SMEM ((24 * WSTR + STAGE_TOT) * 4)   // 164224 B

extern "C" void kernel_launch(void* const* d_in, const int* in_sizes, int n_in,
                              void* d_out, int out_size)
{
    const float* x      = (const float*)d_in[0];
    const float* m_prev = (const float*)d_in[1];
    const float* Wxh    = (const float*)d_in[2];
    const float* Whm    = (const float*)d_in[3];
    const float* Wmm    = (const float*)d_in[4];
    const float* Wmh    = (const float*)d_in[5];
    const float* bh     = (const float*)d_in[6];
    const float* bm     = (const float*)d_in[7];
    float* out = (float*)d_out;

    cudaFuncSetAttribute(prologue_k,
                         cudaFuncAttributeMaxDynamicSharedMemorySize, PRO_SMEM);
    cudaFuncSetAttribute(recur_k,
                         cudaFuncAttributeMaxDynamicSharedMemorySize, PER_SMEM);

    prologue_k<<<dim3(64, 512), 512, PRO_SMEM>>>(x, Wxh, bh);
    recur_k<<<128, 512, PER_SMEM>>>(m_prev, Whm, Wmm, Wmh, bm, out);
}